// round 2
// baseline (speedup 1.0000x reference)
#include <cuda_runtime.h>

// Problem constants (fixed shapes: T=1, C=8, E=4, H=W=64)
#define HP   66            // padded H=W (64+2)
#define QQ   4356          // HP*HP
#define HO   64            // original H=W
#define WSZ  15            // search window side
#define NC   225           // WSZ*WSZ candidates
#define KS   64            // top-k kept
#define KAGG 7             // aggregated volumes
#define BIGD 1e10f

// ---------------- scratch (device globals; no allocation allowed) ------------
__device__ float4 g_pex4[QQ * 16];        // (Q,64) xe patch embeddings
__device__ float4 g_pey4[QQ * 16];        // (Q,64) ye patch embeddings
__device__ float4 g_px4 [QQ * 32];        // (Q,128) x patches
__device__ float4 g_zp4 [QQ * KAGG * 32]; // (Q,7,128) weighted patch sums
__device__ float  g_w   [QQ * 512];       // (Q,64,8) weights, [o*8+k], k<7 used
__device__ int    g_inds[QQ * KS];        // selected candidate pixel indices
__device__ float  g_cn  [QQ];             // ||pex||^2
__device__ float  g_qn  [QQ];             // ||pey||^2
__device__ float  g_tau [QQ];             // exp(avg log_temp patch)

// ---------------- kernel A: xe/ye patch embeddings + norms + temperature -----
__global__ void embed_kernel(const float* __restrict__ xe,
                             const float* __restrict__ ye,
                             const float* __restrict__ ltin) {
    int q = blockIdx.x, tid = threadIdx.x;          // 64 threads
    int qi = q / HP, qj = q % HP;
    int p = tid & 15, e = tid >> 4;
    int a = p >> 2, b = p & 3;
    int i = qi + a - 3, j = qj + b - 3;             // original-image coords
    bool inb = ((unsigned)i < 64u) && ((unsigned)j < 64u);
    float vx = inb ? xe[e * 4096 + i * 64 + j] : 0.f;
    float vy = inb ? ye[e * 4096 + i * 64 + j] : 0.f;
    ((float*)g_pex4)[q * 64 + tid] = vx;
    ((float*)g_pey4)[q * 64 + tid] = vy;

    __shared__ float sm[64];
    sm[tid] = vx * vx; __syncthreads();
    for (int st = 32; st > 0; st >>= 1) { if (tid < st) sm[tid] += sm[tid + st]; __syncthreads(); }
    if (tid == 0) g_cn[q] = sm[0];
    __syncthreads();

    sm[tid] = vy * vy; __syncthreads();
    for (int st = 32; st > 0; st >>= 1) { if (tid < st) sm[tid] += sm[tid + st]; __syncthreads(); }
    if (tid == 0) g_qn[q] = sm[0];
    __syncthreads();

    float lv = 0.f;
    if (tid < 16 && inb) lv = ltin[i * 64 + j];     // tid<16 -> e==0, p==tid
    sm[tid] = lv; __syncthreads();
    for (int st = 32; st > 0; st >>= 1) { if (tid < st) sm[tid] += sm[tid + st]; __syncthreads(); }
    if (tid == 0) g_tau[q] = expf(sm[0] * (1.f / 16.f));
}

// ---------------- kernel B: x patches --------------------------------------
__global__ void px_kernel(const float* __restrict__ x) {
    int q = blockIdx.x, tid = threadIdx.x;          // 128 threads
    int qi = q / HP, qj = q % HP;
    int p = tid & 15, ch = tid >> 4;
    int a = p >> 2, b = p & 3;
    int i = qi + a - 3, j = qj + b - 3;
    bool inb = ((unsigned)i < 64u) && ((unsigned)j < 64u);
    ((float*)g_px4)[q * 128 + tid] = inb ? x[ch * 4096 + i * 64 + j] : 0.f;
}

// ---------------- kernel C: distances + exact top-64 + NNN weights ----------
__global__ void dist_kernel() {
    int q = blockIdx.x, tid = threadIdx.x;          // 256 threads
    int qi = q / HP, qj = q % HP;
    int topr  = min(max(qi - 7, 0), HP - WSZ);
    int leftc = min(max(qj - 7, 0), HP - WSZ);

    __shared__ float4 pey4[16];
    __shared__ float  dvals[256];
    __shared__ unsigned long long keys[256];
    __shared__ float  red[64];

    if (tid < 16) pey4[tid] = g_pey4[q * 16 + tid];
    __syncthreads();

    float d = 1e30f;
    if (tid < NC) {
        int r = topr + tid / WSZ, c = leftc + tid % WSZ;
        int cand = r * HP + c;
        const float4* pv = &g_pex4[cand * 16];
        float acc = 0.f;
        #pragma unroll
        for (int i = 0; i < 16; i++) {
            float4 v = pv[i]; float4 u = pey4[i];
            acc += v.x * u.x + v.y * u.y + v.z * u.z + v.w * u.w;
        }
        d = g_qn[q] + g_cn[cand] - 2.f * acc;
        if (cand == q) d = BIGD;                    // remove_self
    }
    dvals[tid] = d;

    // sortable key: (monotone float bits << 32) | original index (stable ties)
    unsigned u = __float_as_uint(d);
    u = (u & 0x80000000u) ? ~u : (u | 0x80000000u);
    unsigned long long key = ((unsigned long long)u << 32) | (unsigned)tid;
    if (tid >= NC) key = 0xFFFFFFFFFFFFFFFFull;
    keys[tid] = key;
    __syncthreads();

    // bitonic sort 256 ascending (d, index)
    for (int k = 2; k <= 256; k <<= 1)
        for (int j = k >> 1; j > 0; j >>= 1) {
            int ixj = tid ^ j;
            if (ixj > tid) {
                bool up = ((tid & k) == 0);
                unsigned long long A = keys[tid], B = keys[ixj];
                if ((A > B) == up) { keys[tid] = B; keys[ixj] = A; }
            }
            __syncthreads();
        }

    // take 64 nearest; compute logits
    float tau = g_tau[q];
    float logit = 0.f;
    if (tid < KS) {
        int o = (int)(keys[tid] & 0xffffffffull);
        float dd = dvals[o];
        logit = -dd / tau;                          // dists = -L2, / exp(lt)
        int r = topr + o / WSZ, c = leftc + o % WSZ;
        g_inds[q * KS + tid] = r * HP + c;
    }

    // K=7 continuous top-1 relaxations
    for (int k = 0; k < KAGG; k++) {
        if (tid < KS) red[tid] = logit;
        __syncthreads();
        for (int st = 32; st > 0; st >>= 1) { if (tid < st) red[tid] = fmaxf(red[tid], red[tid + st]); __syncthreads(); }
        float m = red[0];
        __syncthreads();
        float ex = 0.f;
        if (tid < KS) { ex = expf(logit - m); red[tid] = ex; }
        __syncthreads();
        for (int st = 32; st > 0; st >>= 1) { if (tid < st) red[tid] += red[tid + st]; __syncthreads(); }
        float ssum = red[0];
        __syncthreads();
        if (tid < KS) {
            float w = ex / ssum;
            g_w[q * 512 + tid * 8 + k] = w;
            logit += logf(fmaxf(1.f - w, 1e-10f));
        }
        __syncthreads();
    }
}

// ---------------- kernel D: zp[q,k,d] = sum_o w[k,o] * px[ind[o], d] ---------
__global__ void zp_kernel() {
    int lane = threadIdx.x;                          // 32 lanes: d4 index
    int ql = threadIdx.y;                            // 4 queries per block
    int q = blockIdx.x * 4 + ql;

    __shared__ float ws[4][512];
    __shared__ int   is[4][64];
    for (int i = lane; i < 512; i += 32) ws[ql][i] = g_w[q * 512 + i];
    for (int i = lane; i < 64;  i += 32) is[ql][i] = g_inds[q * KS + i];
    __syncwarp();

    float4 acc[KAGG];
    #pragma unroll
    for (int k = 0; k < KAGG; k++) acc[k] = make_float4(0.f, 0.f, 0.f, 0.f);

    for (int o = 0; o < KS; o++) {
        int ind = is[ql][o];
        float4 v = g_px4[ind * 32 + lane];
        #pragma unroll
        for (int k = 0; k < KAGG; k++) {
            float w = ws[ql][o * 8 + k];
            acc[k].x += w * v.x; acc[k].y += w * v.y;
            acc[k].z += w * v.z; acc[k].w += w * v.w;
        }
    }
    #pragma unroll
    for (int k = 0; k < KAGG; k++)
        g_zp4[(q * KAGG + k) * 32 + lane] = acc[k];
}

// ---------------- kernel E: fold (gather form) + residual + output ----------
__global__ void fold_kernel(const float* __restrict__ y, float* __restrict__ out) {
    int idx = blockIdx.x * blockDim.x + threadIdx.x;  // 64ch * 64 * 64
    int cho = idx >> 12;
    int rem = idx & 4095;
    int oy = rem >> 6, ox = rem & 63;

    if (cho < 8) { out[idx] = y[cho * 4096 + rem]; return; }

    int kk = (cho - 8) >> 3, ch = (cho - 8) & 7;
    int ti = oy + 1, tj = ox + 1;                    // padded-image coords
    const float* zp = (const float*)g_zp4;
    float sum = 0.f;
    #pragma unroll
    for (int a = 0; a < 4; a++) {
        int qi = ti + 2 - a;
        if (qi >= HP) continue;                      // qi>=0 guaranteed (ti>=1)
        #pragma unroll
        for (int b = 0; b < 4; b++) {
            int qj = tj + 2 - b;
            if (qj >= HP) continue;
            int q = qi * HP + qj;
            sum += zp[q * (KAGG * 128) + kk * 128 + ch * 16 + a * 4 + b];
        }
    }
    float cnti = (ti == HO) ? 3.f : 4.f;
    float cntj = (tj == HO) ? 3.f : 4.f;
    float z = sum / (cnti * cntj + 1e-10f);
    out[idx] = z - y[ch * 4096 + rem];
}

// ---------------- launch -----------------------------------------------------
extern "C" void kernel_launch(void* const* d_in, const int* in_sizes, int n_in,
                              void* d_out, int out_size) {
    const float* x  = (const float*)d_in[0];
    const float* xe = (const float*)d_in[1];
    const float* ye = (const float*)d_in[2];
    const float* y  = (const float*)d_in[3];
    const float* lt = (const float*)d_in[4];
    float* out = (float*)d_out;

    embed_kernel<<<QQ, 64>>>(xe, ye, lt);
    px_kernel  <<<QQ, 128>>>(x);
    dist_kernel<<<QQ, 256>>>();
    zp_kernel  <<<QQ / 4, dim3(32, 4)>>>();
    fold_kernel<<<(64 * 4096) / 256, 256>>>(y, out);
}

// round 5
// speedup vs baseline: 1.6835x; 1.6835x over previous
#include <cuda_runtime.h>

// Problem constants (fixed shapes: T=1, C=8, E=4, H=W=64)
#define HP   66            // padded H=W (64+2)
#define QQ   4356          // HP*HP
#define HO   64            // original H=W
#define WSZ  15            // search window side
#define NC   225           // WSZ*WSZ candidates
#define KS   64            // top-k kept
#define KAGG 7             // aggregated volumes
#define BIGD 1e10f

// ---------------- scratch (device globals; no allocation allowed) ------------
__device__ float4 g_pexT4[16 * QQ];       // xe patch embeddings, TRANSPOSED [chunk][q]
__device__ float4 g_pey4 [QQ * 16];       // (Q,64) ye patch embeddings (row-major)
__device__ float4 g_px4  [QQ * 32];       // (Q,128) x patches
__device__ float4 g_zp4  [QQ * KAGG * 32];// (Q,7,128) weighted patch sums
__device__ float  g_w    [QQ * 512];      // (Q,64,8) weights, [o*8+k], k<7 used
__device__ int    g_inds [QQ * KS];       // selected candidate pixel indices
__device__ float  g_cn   [QQ];            // ||pex||^2
__device__ float  g_qn   [QQ];            // ||pey||^2
__device__ float  g_tau  [QQ];            // exp(avg log_temp patch)

// ---------------- kernel A: patches (x, xe, ye) + norms + temperature --------
__global__ void embed_px_kernel(const float* __restrict__ x,
                                const float* __restrict__ xe,
                                const float* __restrict__ ye,
                                const float* __restrict__ ltin) {
    int q = blockIdx.x, tid = threadIdx.x;          // 128 threads
    int qi = q / HP, qj = q % HP;
    int p = tid & 15, ch = tid >> 4;                // ch: 0..7 (x), 0..3 for tid<64
    int a = p >> 2, b = p & 3;
    int i = qi + a - 3, j = qj + b - 3;             // original-image coords
    bool inb = ((unsigned)i < 64u) && ((unsigned)j < 64u);

    // x patches (all 128 threads)
    ((float*)g_px4)[q * 128 + tid] = inb ? x[ch * 4096 + i * 64 + j] : 0.f;

    __shared__ float sm[64];
    float vx = 0.f, vy = 0.f;
    if (tid < 64) {                                  // d = ch*16 + p = tid
        vx = inb ? xe[ch * 4096 + i * 64 + j] : 0.f;
        vy = inb ? ye[ch * 4096 + i * 64 + j] : 0.f;
        // transposed xe storage: float index chunk*(QQ*4) + q*4 + comp
        ((float*)g_pexT4)[(tid >> 2) * (QQ * 4) + q * 4 + (tid & 3)] = vx;
        ((float*)g_pey4)[q * 64 + tid] = vy;
    }

    if (tid < 64) sm[tid] = vx * vx;
    __syncthreads();
    for (int st = 32; st > 0; st >>= 1) { if (tid < st) sm[tid] += sm[tid + st]; __syncthreads(); }
    if (tid == 0) g_cn[q] = sm[0];
    __syncthreads();

    if (tid < 64) sm[tid] = vy * vy;
    __syncthreads();
    for (int st = 32; st > 0; st >>= 1) { if (tid < st) sm[tid] += sm[tid + st]; __syncthreads(); }
    if (tid == 0) g_qn[q] = sm[0];
    __syncthreads();

    float lv = 0.f;
    if (tid < 16 && inb) lv = ltin[i * 64 + j];      // tid<16 -> ch==0, p==tid
    if (tid < 64) sm[tid] = (tid < 16) ? lv : 0.f;
    __syncthreads();
    for (int st = 32; st > 0; st >>= 1) { if (tid < st) sm[tid] += sm[tid + st]; __syncthreads(); }
    if (tid == 0) g_tau[q] = expf(sm[0] * (1.f / 16.f));
}

// ---------------- kernel B: distances + exact top-64 + NNN weights ----------
__global__ void dist_kernel() {
    int q = blockIdx.x, tid = threadIdx.x;          // 256 threads
    int qi = q / HP, qj = q % HP;
    int topr  = min(max(qi - 7, 0), HP - WSZ);
    int leftc = min(max(qj - 7, 0), HP - WSZ);

    __shared__ float4 pey4[16];
    __shared__ float  dvals[256];
    __shared__ unsigned long long keys[256];

    if (tid < 16) pey4[tid] = g_pey4[q * 16 + tid];
    __syncthreads();

    float d = 1e30f;
    if (tid < NC) {
        int r = topr + tid / WSZ, c = leftc + tid % WSZ;
        int cand = r * HP + c;
        float acc = 0.f;
        #pragma unroll
        for (int i = 0; i < 16; i++) {
            float4 v = g_pexT4[i * QQ + cand];      // lane-contiguous gather
            float4 u = pey4[i];
            acc += v.x * u.x + v.y * u.y + v.z * u.z + v.w * u.w;
        }
        d = g_qn[q] + g_cn[cand] - 2.f * acc;
        if (cand == q) d = BIGD;                    // remove_self
    }
    dvals[tid] = d;

    // sortable key: (monotone float bits << 32) | original index (stable ties)
    unsigned u = __float_as_uint(d);
    u = (u & 0x80000000u) ? ~u : (u | 0x80000000u);
    unsigned long long key = ((unsigned long long)u << 32) | (unsigned)tid;
    if (tid >= NC) key = 0xFFFFFFFFFFFFFFFFull;
    keys[tid] = key;
    __syncthreads();

    // bitonic sort 256 ascending (d, index)
    for (int k = 2; k <= 256; k <<= 1)
        for (int j = k >> 1; j > 0; j >>= 1) {
            int ixj = tid ^ j;
            if (ixj > tid) {
                bool up = ((tid & k) == 0);
                unsigned long long A = keys[tid], B = keys[ixj];
                if ((A > B) == up) { keys[tid] = B; keys[ixj] = A; }
            }
            __syncthreads();
        }

    // warp 0 alone: K=7 continuous top-1 relaxations via shfl (2 logits/lane)
    if (tid < 32) {
        float tau = g_tau[q];
        int o1 = (int)(keys[tid]      & 0xffffffffull);
        int o2 = (int)(keys[tid + 32] & 0xffffffffull);
        float l1 = -dvals[o1] / tau;
        float l2 = -dvals[o2] / tau;
        {
            int r = topr + o1 / WSZ, c = leftc + o1 % WSZ;
            g_inds[q * KS + tid] = r * HP + c;
            r = topr + o2 / WSZ; c = leftc + o2 % WSZ;
            g_inds[q * KS + tid + 32] = r * HP + c;
        }
        #pragma unroll
        for (int k = 0; k < KAGG; k++) {
            float m = fmaxf(l1, l2);
            #pragma unroll
            for (int st = 16; st > 0; st >>= 1)
                m = fmaxf(m, __shfl_xor_sync(0xffffffffu, m, st));
            float e1 = expf(l1 - m), e2 = expf(l2 - m);
            float s = e1 + e2;
            #pragma unroll
            for (int st = 16; st > 0; st >>= 1)
                s += __shfl_xor_sync(0xffffffffu, s, st);
            float w1 = e1 / s, w2 = e2 / s;
            g_w[q * 512 + tid * 8 + k] = w1;
            g_w[q * 512 + (tid + 32) * 8 + k] = w2;
            l1 += logf(fmaxf(1.f - w1, 1e-10f));
            l2 += logf(fmaxf(1.f - w2, 1e-10f));
        }
    }
}

// ---------------- kernel C: zp[q,k,d] = sum_o w[k,o] * px[ind[o], d] ---------
// 128 threads: 2 queries/block, 2 warps per query (o split), f32x2 packed FMA
__global__ void zp_kernel() {
    int tid = threadIdx.x;
    int lane = tid & 31;
    int wid  = tid >> 5;                             // 0..3
    int ql   = wid >> 1;                             // query slot 0/1
    int half = wid & 1;                              // o-half
    int q = blockIdx.x * 2 + ql;

    __shared__ float ws[2][512];
    __shared__ int   is[2][64];
    __shared__ ulonglong2 part[2][KAGG][32];

    int t2 = tid & 63;
    int qslot = tid >> 6;                            // == ql
    int qg = blockIdx.x * 2 + qslot;
    for (int i = t2; i < 512; i += 64) ws[qslot][i] = g_w[qg * 512 + i];
    if (t2 < 64) is[qslot][t2] = g_inds[qg * 64 + t2];
    __syncthreads();

    unsigned long long accA[KAGG], accB[KAGG];
    #pragma unroll
    for (int k = 0; k < KAGG; k++) { accA[k] = 0ull; accB[k] = 0ull; }

    const ulonglong2* px = reinterpret_cast<const ulonglong2*>(g_px4);
    int obase = half * 32;
    for (int oi = 0; oi < 32; oi++) {
        int o = obase + oi;
        int ind = is[ql][o];
        ulonglong2 v = px[ind * 32 + lane];          // float4 as 2 packed f32x2
        const float* wrow = &ws[ql][o * 8];
        #pragma unroll
        for (int k = 0; k < KAGG; k++) {
            float wv = wrow[k];
            unsigned long long wd;
            asm("mov.b64 %0, {%1, %1};" : "=l"(wd) : "f"(wv));
            asm("fma.rn.f32x2 %0, %1, %2, %0;" : "+l"(accA[k]) : "l"(v.x), "l"(wd));
            asm("fma.rn.f32x2 %0, %1, %2, %0;" : "+l"(accB[k]) : "l"(v.y), "l"(wd));
        }
    }

    if (half == 1) {
        #pragma unroll
        for (int k = 0; k < KAGG; k++)
            part[ql][k][lane] = make_ulonglong2(accA[k], accB[k]);
    }
    __syncthreads();
    if (half == 0) {
        ulonglong2* zp = reinterpret_cast<ulonglong2*>(g_zp4);
        #pragma unroll
        for (int k = 0; k < KAGG; k++) {
            ulonglong2 pb = part[ql][k][lane];
            unsigned long long a = accA[k], b = accB[k];
            asm("add.rn.f32x2 %0, %0, %1;" : "+l"(a) : "l"(pb.x));
            asm("add.rn.f32x2 %0, %0, %1;" : "+l"(b) : "l"(pb.y));
            zp[(q * KAGG + k) * 32 + lane] = make_ulonglong2(a, b);
        }
    }
}

// ---------------- kernel D: fold (gather form) + residual + output ----------
__global__ void fold_kernel(const float* __restrict__ y, float* __restrict__ out) {
    int idx = blockIdx.x * blockDim.x + threadIdx.x;  // 64ch * 64 * 64
    int cho = idx >> 12;
    int rem = idx & 4095;
    int oy = rem >> 6, ox = rem & 63;

    if (cho < 8) { out[idx] = y[cho * 4096 + rem]; return; }

    int kk = (cho - 8) >> 3, ch = (cho - 8) & 7;
    int ti = oy + 1, tj = ox + 1;                    // padded-image coords
    const float* zp = (const float*)g_zp4;
    float sum = 0.f;
    #pragma unroll
    for (int a = 0; a < 4; a++) {
        int qi = ti + 2 - a;
        if (qi >= HP) continue;                      // qi>=0 guaranteed (ti>=1)
        #pragma unroll
        for (int b = 0; b < 4; b++) {
            int qj = tj + 2 - b;
            if (qj >= HP) continue;
            int q = qi * HP + qj;
            sum += zp[q * (KAGG * 128) + kk * 128 + ch * 16 + a * 4 + b];
        }
    }
    float cnti = (ti == HO) ? 3.f : 4.f;
    float cntj = (tj == HO) ? 3.f : 4.f;
    float z = sum / (cnti * cntj + 1e-10f);
    out[idx] = z - y[ch * 4096 + rem];
}

// ---------------- launch -----------------------------------------------------
extern "C" void kernel_launch(void* const* d_in, const int* in_sizes, int n_in,
                              void* d_out, int out_size) {
    const float* x  = (const float*)d_in[0];
    const float* xe = (const float*)d_in[1];
    const float* ye = (const float*)d_in[2];
    const float* y  = (const float*)d_in[3];
    const float* lt = (const float*)d_in[4];
    float* out = (float*)d_out;

    embed_px_kernel<<<QQ, 128>>>(x, xe, ye, lt);
    dist_kernel    <<<QQ, 256>>>();
    zp_kernel      <<<QQ / 2, 128>>>();
    fold_kernel    <<<(64 * 4096) / 256, 256>>>(y, out);
}

// round 6
// speedup vs baseline: 1.7746x; 1.0541x over previous
#include <cuda_runtime.h>

// Problem constants (fixed shapes: T=1, C=8, E=4, H=W=64)
#define HP   66            // padded H=W (64+2)
#define QQ   4356          // HP*HP
#define HO   64            // original H=W
#define WSZ  15            // search window side
#define NC   225           // WSZ*WSZ candidates
#define KS   64            // top-k kept
#define KAGG 7             // aggregated volumes
#define BIGD 1e10f

// ---------------- scratch (device globals; no allocation allowed) ------------
__device__ float4 g_pexT4[16 * QQ];       // xe patch embeddings, TRANSPOSED [chunk][q]
__device__ float4 g_pey4 [QQ * 16];       // (Q,64) ye patch embeddings (row-major)
__device__ float4 g_px4  [QQ * 32];       // (Q,128) x patches
__device__ float4 g_zp4  [QQ * KAGG * 32];// (Q,7,128) weighted patch sums
__device__ float  g_w    [QQ * 512];      // (Q,64,8) weights, [o*8+k], k<7 used
__device__ int    g_inds [QQ * KS];       // selected candidate pixel indices
__device__ float  g_qn   [QQ];            // ||pey||^2
__device__ float  g_tau  [QQ];            // exp(avg log_temp patch)

// ---------------- kernel A: patches (x, xe, ye) + norms + temperature --------
__global__ void embed_px_kernel(const float* __restrict__ x,
                                const float* __restrict__ xe,
                                const float* __restrict__ ye,
                                const float* __restrict__ ltin) {
    int q = blockIdx.x, tid = threadIdx.x;          // 128 threads
    int qi = q / HP, qj = q % HP;
    int p = tid & 15, ch = tid >> 4;                // ch: 0..7 (x), 0..3 for tid<64
    int a = p >> 2, b = p & 3;
    int i = qi + a - 3, j = qj + b - 3;             // original-image coords
    bool inb = ((unsigned)i < 64u) && ((unsigned)j < 64u);

    // x patches (all 128 threads)
    ((float*)g_px4)[q * 128 + tid] = inb ? x[ch * 4096 + i * 64 + j] : 0.f;

    __shared__ float sm[64];
    float vy = 0.f;
    if (tid < 64) {                                  // d = ch*16 + p = tid
        float vx = inb ? xe[ch * 4096 + i * 64 + j] : 0.f;
        vy = inb ? ye[ch * 4096 + i * 64 + j] : 0.f;
        // transposed xe storage: float index chunk*(QQ*4) + q*4 + comp
        ((float*)g_pexT4)[(tid >> 2) * (QQ * 4) + q * 4 + (tid & 3)] = vx;
        ((float*)g_pey4)[q * 64 + tid] = vy;
    }

    if (tid < 64) sm[tid] = vy * vy;
    __syncthreads();
    for (int st = 32; st > 0; st >>= 1) { if (tid < st) sm[tid] += sm[tid + st]; __syncthreads(); }
    if (tid == 0) g_qn[q] = sm[0];
    __syncthreads();

    float lv = 0.f;
    if (tid < 16 && inb) lv = ltin[i * 64 + j];      // tid<16 -> ch==0, p==tid
    if (tid < 64) sm[tid] = (tid < 16) ? lv : 0.f;
    __syncthreads();
    for (int st = 32; st > 0; st >>= 1) { if (tid < st) sm[tid] += sm[tid + st]; __syncthreads(); }
    if (tid == 0) g_tau[q] = expf(sm[0] * (1.f / 16.f));
}

// ---------------- kernel B: tiled distances + top-64 + NNN weights ----------
// One block = 2x2 query tile. Shared 16x16 candidate-window union staged in
// smem (two passes of 8 float4-chunks), candidate norms computed during load.
__global__ void dist_kernel() {
    int tid = threadIdx.x;                           // 256 threads
    int bi = blockIdx.x;                             // 33*33 tiles
    int tile_i = (bi / 33) * 2, tile_j = (bi % 33) * 2;

    __shared__ float4 wsm[8][256];                   // 32KB window chunk-slab
    __shared__ float  dv [4][256];                   // cross / final dists
    __shared__ unsigned long long keys[4][256];      // 8KB sort keys
    __shared__ float  cns[256];                      // candidate norms
    __shared__ float4 peys[4][16];                   // query embeddings

    int topr0  = min(max(tile_i - 7, 0), HP - WSZ);
    int leftc0 = min(max(tile_j - 7, 0), HP - WSZ);

    // per-query window anchors (offset 0/1 from union base)
    int toprl[4], leftcl[4], qpix[4];
    #pragma unroll
    for (int ql = 0; ql < 4; ql++) {
        int qi = tile_i + (ql >> 1), qj = tile_j + (ql & 1);
        toprl[ql]  = min(max(qi - 7, 0), HP - WSZ);
        leftcl[ql] = min(max(qj - 7, 0), HP - WSZ);
        qpix[ql]   = qi * HP + qj;
    }

    if (tid < 64) peys[tid >> 4][tid & 15] = g_pey4[qpix[tid >> 4] * 16 + (tid & 15)];

    // candidate pixel for this thread (clamped; clamped slots never referenced)
    int crow = min(topr0 + (tid >> 4), HP - 1);
    int ccol = min(leftc0 + (tid & 15), HP - 1);
    int cpix = crow * HP + ccol;

    float cnacc = 0.f;
    float crossA[4];

    // ---- pass 0: chunks 0..7 ----
    #pragma unroll
    for (int i = 0; i < 8; i++) {
        float4 v = g_pexT4[i * QQ + cpix];
        wsm[i][tid] = v;
        cnacc += v.x * v.x + v.y * v.y + v.z * v.z + v.w * v.w;
    }
    __syncthreads();
    {
        int wr = tid / WSZ, wc = tid - wr * WSZ;     // window-local coords
        #pragma unroll
        for (int ql = 0; ql < 4; ql++) {
            float acc = 0.f;
            if (tid < NC) {
                int cidx = (wr + toprl[ql] - topr0) * 16 + (wc + leftcl[ql] - leftc0);
                #pragma unroll
                for (int i = 0; i < 8; i++) {
                    float4 v = wsm[i][cidx]; float4 u = peys[ql][i];
                    acc += v.x * u.x + v.y * u.y + v.z * u.z + v.w * u.w;
                }
            }
            crossA[ql] = acc;
        }
    }
    __syncthreads();

    // ---- pass 1: chunks 8..15 ----
    #pragma unroll
    for (int i = 0; i < 8; i++) {
        float4 v = g_pexT4[(8 + i) * QQ + cpix];
        wsm[i][tid] = v;
        cnacc += v.x * v.x + v.y * v.y + v.z * v.z + v.w * v.w;
    }
    cns[tid] = cnacc;
    __syncthreads();
    {
        int wr = tid / WSZ, wc = tid - wr * WSZ;
        #pragma unroll
        for (int ql = 0; ql < 4; ql++) {
            float d = 1e30f;
            if (tid < NC) {
                int cidx = (wr + toprl[ql] - topr0) * 16 + (wc + leftcl[ql] - leftc0);
                float acc = crossA[ql];
                #pragma unroll
                for (int i = 0; i < 8; i++) {
                    float4 v = wsm[i][cidx]; float4 u = peys[ql][8 + i];
                    acc += v.x * u.x + v.y * u.y + v.z * u.z + v.w * u.w;
                }
                int pr = toprl[ql] + wr, pc = leftcl[ql] + wc;
                int pix = pr * HP + pc;
                d = g_qn[qpix[ql]] + cns[cidx] - 2.f * acc;
                if (pix == qpix[ql]) d = BIGD;       // remove_self
            }
            dv[ql][tid] = d;
            unsigned u = __float_as_uint(d);
            u = (u & 0x80000000u) ? ~u : (u | 0x80000000u);
            unsigned long long key = ((unsigned long long)u << 32) | (unsigned)tid;
            if (tid >= NC) key = 0xFFFFFFFFFFFFFFFFull;
            keys[ql][tid] = key;
        }
    }
    __syncthreads();

    // ---- bitonic sort: 4 independent 256-segments, barriers amortized ----
    for (int k = 2; k <= 256; k <<= 1)
        for (int j = k >> 1; j > 0; j >>= 1) {
            int ixj = tid ^ j;
            if (ixj > tid) {
                bool up = ((tid & k) == 0);
                #pragma unroll
                for (int ql = 0; ql < 4; ql++) {
                    unsigned long long A = keys[ql][tid], B = keys[ql][ixj];
                    if ((A > B) == up) { keys[ql][tid] = B; keys[ql][ixj] = A; }
                }
            }
            __syncthreads();
        }

    // ---- epilogue: warps 0..3, one query each; K=7 relaxations via shfl ----
    int wq = tid >> 5, lane = tid & 31;
    if (wq < 4) {
        int ql = wq;
        int q = qpix[ql];
        float tau = g_tau[q];
        int o1 = (int)(keys[ql][lane]      & 0xffffffffull);
        int o2 = (int)(keys[ql][lane + 32] & 0xffffffffull);
        float l1 = -dv[ql][o1] / tau;
        float l2 = -dv[ql][o2] / tau;
        {
            int r = toprl[ql] + o1 / WSZ, c = leftcl[ql] + o1 % WSZ;
            g_inds[q * KS + lane] = r * HP + c;
            r = toprl[ql] + o2 / WSZ; c = leftcl[ql] + o2 % WSZ;
            g_inds[q * KS + lane + 32] = r * HP + c;
        }
        #pragma unroll
        for (int k = 0; k < KAGG; k++) {
            float m = fmaxf(l1, l2);
            #pragma unroll
            for (int st = 16; st > 0; st >>= 1)
                m = fmaxf(m, __shfl_xor_sync(0xffffffffu, m, st));
            float e1 = expf(l1 - m), e2 = expf(l2 - m);
            float s = e1 + e2;
            #pragma unroll
            for (int st = 16; st > 0; st >>= 1)
                s += __shfl_xor_sync(0xffffffffu, s, st);
            float w1 = e1 / s, w2 = e2 / s;
            g_w[q * 512 + lane * 8 + k] = w1;
            g_w[q * 512 + (lane + 32) * 8 + k] = w2;
            l1 += logf(fmaxf(1.f - w1, 1e-10f));
            l2 += logf(fmaxf(1.f - w2, 1e-10f));
        }
    }
}

// ---------------- kernel C: zp[q,k,d] = sum_o w[k,o] * px[ind[o], d] ---------
// 128 threads: 2 queries/block, 2 warps per query (o split), f32x2 packed FMA
__global__ void zp_kernel() {
    int tid = threadIdx.x;
    int lane = tid & 31;
    int wid  = tid >> 5;                             // 0..3
    int ql   = wid >> 1;                             // query slot 0/1
    int half = wid & 1;                              // o-half
    int q = blockIdx.x * 2 + ql;

    __shared__ float ws[2][512];
    __shared__ int   is[2][64];
    __shared__ ulonglong2 part[2][KAGG][32];

    int t2 = tid & 63;
    int qslot = tid >> 6;                            // == ql
    int qg = blockIdx.x * 2 + qslot;
    for (int i = t2; i < 512; i += 64) ws[qslot][i] = g_w[qg * 512 + i];
    if (t2 < 64) is[qslot][t2] = g_inds[qg * 64 + t2];
    __syncthreads();

    unsigned long long accA[KAGG], accB[KAGG];
    #pragma unroll
    for (int k = 0; k < KAGG; k++) { accA[k] = 0ull; accB[k] = 0ull; }

    const ulonglong2* px = reinterpret_cast<const ulonglong2*>(g_px4);
    int obase = half * 32;
    for (int oi = 0; oi < 32; oi++) {
        int o = obase + oi;
        int ind = is[ql][o];
        ulonglong2 v = px[ind * 32 + lane];          // float4 as 2 packed f32x2
        const float* wrow = &ws[ql][o * 8];
        #pragma unroll
        for (int k = 0; k < KAGG; k++) {
            float wv = wrow[k];
            unsigned long long wd;
            asm("mov.b64 %0, {%1, %1};" : "=l"(wd) : "f"(wv));
            asm("fma.rn.f32x2 %0, %1, %2, %0;" : "+l"(accA[k]) : "l"(v.x), "l"(wd));
            asm("fma.rn.f32x2 %0, %1, %2, %0;" : "+l"(accB[k]) : "l"(v.y), "l"(wd));
        }
    }

    if (half == 1) {
        #pragma unroll
        for (int k = 0; k < KAGG; k++)
            part[ql][k][lane] = make_ulonglong2(accA[k], accB[k]);
    }
    __syncthreads();
    if (half == 0) {
        ulonglong2* zp = reinterpret_cast<ulonglong2*>(g_zp4);
        #pragma unroll
        for (int k = 0; k < KAGG; k++) {
            ulonglong2 pb = part[ql][k][lane];
            unsigned long long a = accA[k], b = accB[k];
            asm("add.rn.f32x2 %0, %0, %1;" : "+l"(a) : "l"(pb.x));
            asm("add.rn.f32x2 %0, %0, %1;" : "+l"(b) : "l"(pb.y));
            zp[(q * KAGG + k) * 32 + lane] = make_ulonglong2(a, b);
        }
    }
}

// ---------------- kernel D: fold, channel-as-lane mapping -------------------
__global__ void fold_kernel(const float* __restrict__ y, float* __restrict__ out) {
    int idx = blockIdx.x * blockDim.x + threadIdx.x;  // lane = channel (cho)
    int cho = idx & 63;
    int pix = idx >> 6;                               // oy*64+ox
    int oy = pix >> 6, ox = pix & 63;

    if (cho < 8) { out[cho * 4096 + pix] = y[cho * 4096 + pix]; return; }

    int kk = (cho - 8) >> 3, ch = (cho - 8) & 7;
    int ti = oy + 1, tj = ox + 1;                    // padded-image coords
    const float* zp = (const float*)g_zp4;
    float sum = 0.f;
    #pragma unroll
    for (int a = 0; a < 4; a++) {
        int qi = ti + 2 - a;
        if (qi >= HP) continue;                      // qi>=0 guaranteed (ti>=1)
        #pragma unroll
        for (int b = 0; b < 4; b++) {
            int qj = tj + 2 - b;
            if (qj >= HP) continue;
            int q = qi * HP + qj;
            sum += zp[q * (KAGG * 128) + kk * 128 + ch * 16 + a * 4 + b];
        }
    }
    float cnti = (ti == HO) ? 3.f : 4.f;
    float cntj = (tj == HO) ? 3.f : 4.f;
    float z = sum / (cnti * cntj + 1e-10f);
    out[cho * 4096 + pix] = z - y[ch * 4096 + pix];
}

// ---------------- launch -----------------------------------------------------
extern "C" void kernel_launch(void* const* d_in, const int* in_sizes, int n_in,
                              void* d_out, int out_size) {
    const float* x  = (const float*)d_in[0];
    const float* xe = (const float*)d_in[1];
    const float* ye = (const float*)d_in[2];
    const float* y  = (const float*)d_in[3];
    const float* lt = (const float*)d_in[4];
    float* out = (float*)d_out;

    embed_px_kernel<<<QQ, 128>>>(x, xe, ye, lt);
    dist_kernel    <<<33 * 33, 256>>>();
    zp_kernel      <<<QQ / 2, 128>>>();
    fold_kernel    <<<(64 * 4096) / 256, 256>>>(y, out);
}